// round 5
// baseline (speedup 1.0000x reference)
#include <cuda_runtime.h>
#include <cuda_fp16.h>
#include <cstdint>
#include <cstddef>

// ---------------------------------------------------------------------------
// Problem constants
// ---------------------------------------------------------------------------
#define HIDDEN   768
#define META     25
#define ED_COUNT 300
#define BATCH    2
#define N_MENT   2000
#define N_PAIRS  40000
#define M_TOTAL  (BATCH * N_MENT)        // 4000
#define N_TOTAL  (2 * HIDDEN)            // 1536
#define P_TOTAL  (BATCH * N_PAIRS)       // 80000

// ---------------------------------------------------------------------------
// Device scratch
// ---------------------------------------------------------------------------
__device__ __half g_ACh[(size_t)M_TOTAL * N_TOTAL];     // 12.3 MB
__device__ __half g_Eh[(size_t)ED_COUNT * HIDDEN];      // 0.46 MB
__device__ uint32_t g_At[(size_t)M_TOTAL * HIDDEN];     // 12.3 MB tf32, k-paired
__device__ uint32_t g_Bt[(size_t)N_TOTAL * HIDDEN];     //  4.7 MB tf32, [n][k] k-paired

// ---------------------------------------------------------------------------
// helpers
// ---------------------------------------------------------------------------
__device__ __forceinline__ uint32_t smem_u32(const void* p) {
    uint32_t a;
    asm("{ .reg .u64 t; cvta.to.shared.u64 t, %1; cvt.u32.u64 %0, t; }" : "=r"(a) : "l"(p));
    return a;
}
__device__ __forceinline__ void cp_async16(uint32_t dst, const void* src, uint32_t src_bytes) {
    asm volatile("cp.async.ca.shared.global [%0], [%1], 16, %2;"
                 :: "r"(dst), "l"(src), "r"(src_bytes) : "memory");
}
__device__ __forceinline__ uint32_t f2tf32(float f) {
    uint32_t u;
    asm("cvt.rna.tf32.f32 %0, %1;" : "=r"(u) : "f"(f));
    return u;
}
__device__ __forceinline__ void mma_tf32(float* c, const uint32_t* a, const uint32_t* b) {
    asm volatile(
        "mma.sync.aligned.m16n8k8.row.col.f32.tf32.tf32.f32 "
        "{%0,%1,%2,%3}, {%4,%5,%6,%7}, {%8,%9}, {%0,%1,%2,%3};"
        : "+f"(c[0]), "+f"(c[1]), "+f"(c[2]), "+f"(c[3])
        : "r"(a[0]), "r"(a[1]), "r"(a[2]), "r"(a[3]), "r"(b[0]), "r"(b[1]));
}

// ---------------------------------------------------------------------------
// Prep kernels: fp32 -> tf32 with k-pairing  [k0,k4,k1,k5,k2,k6,k3,k7]
// dst j in 8-block reads src k = (j&1)*4 + (j>>1)
// ---------------------------------------------------------------------------
__global__ __launch_bounds__(256)
void prep_a(const float* __restrict__ A)     // [4000,768]
{
    int i = blockIdx.x * 256 + threadIdx.x;
    if (i >= M_TOTAL * HIDDEN) return;
    int j = i & 767;
    int src = (j & ~7) | (((j & 1) << 2) | ((j >> 1) & 3));
    g_At[i] = f2tf32(A[(i & ~767) | src]);
}

// g_Bt[n][kp] = tf32(W1[(n>=768)*768 + k][n%768]),  kp = paired(k)
__global__ void prep_b(const float* __restrict__ W1)
{
    __shared__ float t[32][33];
    const int kt = blockIdx.x;              // 0..23  (k tile within half)
    const int nt = blockIdx.y;              // 0..47  (global n tile)
    const int half = (nt * 32) >= HIDDEN;
    const int nloc = nt * 32 - half * HIDDEN;
    const int c = threadIdx.x;
    for (int r = threadIdx.y; r < 32; r += 8)
        t[r][c] = W1[(size_t)(half * HIDDEN + kt * 32 + r) * HIDDEN + nloc + c];
    __syncthreads();
    for (int rr = threadIdx.y; rr < 32; rr += 8) {
        float v = t[c][rr];                 // = W1[.. + kt*32 + c][nloc + rr]
        int k = kt * 32 + c;
        int kp = (k & ~7) | (((k & 3) << 1) | ((k >> 2) & 1));
        g_Bt[(size_t)(nt * 32 + rr) * HIDDEN + kp] = f2tf32(v);
    }
}

// ---------------------------------------------------------------------------
// tf32 GEMM: 128m x 64n tile, 256 thr (warps 4x2, warp tile 32x32), BK=16,
// 2-stage cp.async, pre-converted k-paired operands, all frag loads LDS.64.
// ---------------------------------------------------------------------------
#define ASTR 24          // words/row (16 data + 8 pad) — conflict-free LDS.64

__global__ __launch_bounds__(256, 3)
void gemm_tc_kernel()
{
    __shared__ __align__(16) uint32_t As[2][128 * ASTR];   // 12.3 KB ea
    __shared__ __align__(16) uint32_t Bs[2][64 * ASTR];    //  6.1 KB ea

    const int tid  = threadIdx.x;
    const int wid  = tid >> 5;
    const int lane = tid & 31;
    const int gid  = lane >> 2;
    const int tig  = lane & 3;

    const int nbase = blockIdx.x * 64;
    const int mbase = blockIdx.y * 128;
    const int wm = (wid & 3) * 32;
    const int wn = (wid >> 2) * 32;

    // cp.async mappings: A 512 chunks (2/thr), B 256 chunks (1/thr)
    const int lrow = tid >> 2;              // 0..63
    const int lq   = (tid & 3) * 4;         // word quarter
    const uint32_t aby0 = (mbase + lrow      < M_TOTAL) ? 16u : 0u;
    const uint32_t aby1 = (mbase + lrow + 64 < M_TOTAL) ? 16u : 0u;
    const uint32_t* a_src0 = g_At + (size_t)(mbase + lrow) * HIDDEN + lq;
    const uint32_t* a_src1 = g_At + (size_t)(mbase + lrow + 64) * HIDDEN + lq;
    const uint32_t* b_src  = g_Bt + (size_t)(nbase + lrow) * HIDDEN + lq;
    uint32_t a_d0[2], a_d1[2], b_d[2];
    a_d0[0] = smem_u32(&As[0][lrow * ASTR + lq]);
    a_d0[1] = smem_u32(&As[1][lrow * ASTR + lq]);
    a_d1[0] = smem_u32(&As[0][(lrow + 64) * ASTR + lq]);
    a_d1[1] = smem_u32(&As[1][(lrow + 64) * ASTR + lq]);
    b_d[0]  = smem_u32(&Bs[0][lrow * ASTR + lq]);
    b_d[1]  = smem_u32(&Bs[1][lrow * ASTR + lq]);

    float acc[2][4][4];
#pragma unroll
    for (int mt = 0; mt < 2; mt++)
#pragma unroll
        for (int nt = 0; nt < 4; nt++)
#pragma unroll
            for (int r = 0; r < 4; r++) acc[mt][nt][r] = 0.f;

    auto load_stage = [&](int kc) {
        const int buf = kc & 1;
        const int k0 = kc * 16;
        cp_async16(a_d0[buf], a_src0 + k0, aby0);
        cp_async16(a_d1[buf], a_src1 + k0, aby1);
        cp_async16(b_d[buf],  b_src  + k0, 16u);
        asm volatile("cp.async.commit_group;" ::: "memory");
    };

    load_stage(0);

    for (int kc = 0; kc < HIDDEN / 16; kc++) {
        if (kc + 1 < HIDDEN / 16) {
            load_stage(kc + 1);
            asm volatile("cp.async.wait_group 1;" ::: "memory");
        } else {
            asm volatile("cp.async.wait_group 0;" ::: "memory");
        }
        __syncthreads();

        const int buf = kc & 1;
        const uint32_t* as = As[buf];
        const uint32_t* bs = Bs[buf];
#pragma unroll
        for (int ks = 0; ks < 2; ks++) {
            const int kk = ks * 8 + 2 * tig;
            uint32_t af[2][4], bf[4][2];
#pragma unroll
            for (int mt = 0; mt < 2; mt++) {
                uint2 r0 = *(const uint2*)(as + (wm + mt * 16 + gid) * ASTR + kk);
                uint2 r1 = *(const uint2*)(as + (wm + mt * 16 + gid + 8) * ASTR + kk);
                af[mt][0] = r0.x; af[mt][1] = r1.x; af[mt][2] = r0.y; af[mt][3] = r1.y;
            }
#pragma unroll
            for (int nt = 0; nt < 4; nt++) {
                uint2 rb = *(const uint2*)(bs + (wn + nt * 8 + gid) * ASTR + kk);
                bf[nt][0] = rb.x; bf[nt][1] = rb.y;
            }
#pragma unroll
            for (int mt = 0; mt < 2; mt++)
#pragma unroll
                for (int nt = 0; nt < 4; nt++)
                    mma_tf32(acc[mt][nt], af[mt], bf[nt]);
        }
        __syncthreads();
    }

    // epilogue -> fp16
#pragma unroll
    for (int mt = 0; mt < 2; mt++) {
        const int m0 = mbase + wm + mt * 16 + gid;
#pragma unroll
        for (int nt = 0; nt < 4; nt++) {
            const int n0 = nbase + wn + nt * 8 + 2 * tig;
            if (m0 < M_TOTAL)
                *(__half2*)(g_ACh + (size_t)m0 * N_TOTAL + n0)
                    = __floats2half2_rn(acc[mt][nt][0], acc[mt][nt][1]);
            if (m0 + 8 < M_TOTAL)
                *(__half2*)(g_ACh + (size_t)(m0 + 8) * N_TOTAL + n0)
                    = __floats2half2_rn(acc[mt][nt][2], acc[mt][nt][3]);
        }
    }
}

// ---------------------------------------------------------------------------
// ed kernel (j-tiled, smem cached)
// ---------------------------------------------------------------------------
#define ED_JTILE 32

__global__ __launch_bounds__(128)
void ed_kernel(const float* __restrict__ ed_table,
               const float* __restrict__ W1,
               const float* __restrict__ b1)
{
    __shared__ float s_ed[ED_COUNT * META];
    __shared__ float s_w[META * ED_JTILE];
    const int tid = threadIdx.x;
    const int jbase = blockIdx.x * ED_JTILE;

    for (int i = tid; i < ED_COUNT * META; i += 128) s_ed[i] = ed_table[i];
    for (int i = tid; i < META * ED_JTILE; i += 128) {
        const int t = i / ED_JTILE, j = i % ED_JTILE;
        s_w[i] = W1[(size_t)(2 * HIDDEN + t) * HIDDEN + jbase + j];
    }
    __syncthreads();

    const int jcol = tid & 31;
    const int erow0 = tid >> 5;
    const float bias = b1[jbase + jcol];
    for (int e = erow0; e < ED_COUNT; e += 4) {
        float s = bias;
        const float* ed = s_ed + e * META;
#pragma unroll
        for (int t = 0; t < META; t++)
            s = fmaf(ed[t], s_w[t * ED_JTILE + jcol], s);
        g_Eh[(size_t)e * HIDDEN + jbase + jcol] = __float2half_rn(s);
    }
}

// ---------------------------------------------------------------------------
// pair kernel (fp16 rows, fp32 math)
// ---------------------------------------------------------------------------
__device__ __forceinline__ float2 h2f(uint32_t u) {
    __half2 h = *reinterpret_cast<__half2*>(&u);
    return __half22float2(h);
}

__global__ __launch_bounds__(256)
void pair_kernel(const int*   __restrict__ pairs,
                 const int*   __restrict__ eds,
                 const float* __restrict__ W2,
                 const float* __restrict__ b2,
                 float*       __restrict__ out)
{
    const int p = blockIdx.x * 8 + (threadIdx.x >> 5);
    if (p >= P_TOTAL) return;
    const int lane = threadIdx.x & 31;

    const int b  = p / N_PAIRS;
    const int i1 = pairs[2 * p];
    const int i2 = pairs[2 * p + 1];
    const int ed = eds[p];

    const uint4* Arow = (const uint4*)(g_ACh + (size_t)(b * N_MENT + i1) * N_TOTAL);
    const uint4* Crow = (const uint4*)(g_ACh + (size_t)(b * N_MENT + i2) * N_TOTAL + HIDDEN);
    const uint4* Erow = (const uint4*)(g_Eh  + (size_t)ed * HIDDEN);
    const float4* Wrow = (const float4*)W2;

    float acc = 0.f;
#pragma unroll
    for (int i = 0; i < HIDDEN / 8 / 32; i++) {
        const int idx = lane + i * 32;
        uint4 a = Arow[idx];
        uint4 c = Crow[idx];
        uint4 e = Erow[idx];
        float4 w0 = Wrow[2 * idx];
        float4 w1 = Wrow[2 * idx + 1];
        float2 fa, fc, fe;
        float h;
        fa = h2f(a.x); fc = h2f(c.x); fe = h2f(e.x);
        h = fa.x + fc.x + fe.x; if (h > 0.f) acc = fmaf(h, w0.x, acc);
        h = fa.y + fc.y + fe.y; if (h > 0.f) acc = fmaf(h, w0.y, acc);
        fa = h2f(a.y); fc = h2f(c.y); fe = h2f(e.y);
        h = fa.x + fc.x + fe.x; if (h > 0.f) acc = fmaf(h, w0.z, acc);
        h = fa.y + fc.y + fe.y; if (h > 0.f) acc = fmaf(h, w0.w, acc);
        fa = h2f(a.z); fc = h2f(c.z); fe = h2f(e.z);
        h = fa.x + fc.x + fe.x; if (h > 0.f) acc = fmaf(h, w1.x, acc);
        h = fa.y + fc.y + fe.y; if (h > 0.f) acc = fmaf(h, w1.y, acc);
        fa = h2f(a.w); fc = h2f(c.w); fe = h2f(e.w);
        h = fa.x + fc.x + fe.x; if (h > 0.f) acc = fmaf(h, w1.z, acc);
        h = fa.y + fc.y + fe.y; if (h > 0.f) acc = fmaf(h, w1.w, acc);
    }
#pragma unroll
    for (int off = 16; off; off >>= 1)
        acc += __shfl_xor_sync(0xffffffffu, acc, off);
    if (lane == 0) out[p] = acc + b2[0];
}

// ---------------------------------------------------------------------------
// Launch
// ---------------------------------------------------------------------------
extern "C" void kernel_launch(void* const* d_in, const int* in_sizes, int n_in,
                              void* d_out, int out_size)
{
    const float* mention  = (const float*)d_in[0];
    const int*   pairs    = (const int*)  d_in[1];
    const int*   eds      = (const int*)  d_in[2];
    const float* ed_table = (const float*)d_in[3];
    const float* W1       = (const float*)d_in[4];
    const float* b1       = (const float*)d_in[5];
    const float* W2       = (const float*)d_in[6];
    const float* b2       = (const float*)d_in[7];
    float* out = (float*)d_out;
    (void)in_sizes; (void)n_in; (void)out_size;

    prep_a<<<(M_TOTAL * HIDDEN + 255) / 256, 256>>>(mention);
    {
        dim3 g(HIDDEN / 32, N_TOTAL / 32);       // (24, 48)
        dim3 t(32, 8);
        prep_b<<<g, t>>>(W1);
    }
    ed_kernel<<<HIDDEN / ED_JTILE, 128>>>(ed_table, W1, b1);
    {
        dim3 g(N_TOTAL / 64, (M_TOTAL + 127) / 128);   // (24, 32) = 768 CTAs
        gemm_tc_kernel<<<g, 256>>>();
    }
    pair_kernel<<<(P_TOTAL + 7) / 8, 256>>>(pairs, eds, W2, b2, out);
}